// round 12
// baseline (speedup 1.0000x reference)
#include <cuda_runtime.h>
#include <cuda_bf16.h>
#include <cstdint>

#define N_NODES 8192
#define E_EDGES 262144
#define IN_DIM  128
#define HID     64
#define ELLW    96     // max in-degree capacity (deg ~ Poisson(32); P(>96) ~ 1e-19)

// ---------------- scratch (device globals; zero-initialized at load) -------
__device__ __align__(16) int           g_cnt[N_NODES];          // in-degree; re-zeroed by gather<2>
__device__ __align__(16) int           g_ell[N_NODES * ELLW];   // src ids, ELL layout
__device__ __align__(16) float         g_hs [N_NODES * HID];    // dinv-scaled X@W
__device__ __align__(16) float         g_h1 [N_NODES * HID];    // layer-1 output
__device__ __align__(16) __nv_bfloat16 g_hb [N_NODES * HID];    // layer-2 output (bf16)

// ---------------- ELL build (single pass; g_cnt starts at 0) ---------------
__global__ void k_ell(const int* __restrict__ ei) {
    int t = blockIdx.x * blockDim.x + threadIdx.x;        // t < E/4
    int4 sv = ((const int4*)ei)[t];
    int4 dv = ((const int4*)(ei + E_EDGES))[t];
    int p0 = atomicAdd(&g_cnt[dv.x], 1);
    int p1 = atomicAdd(&g_cnt[dv.y], 1);
    int p2 = atomicAdd(&g_cnt[dv.z], 1);
    int p3 = atomicAdd(&g_cnt[dv.w], 1);
    g_ell[dv.x * ELLW + p0] = sv.x;
    g_ell[dv.y * ELLW + p1] = sv.y;
    g_ell[dv.z * ELLW + p2] = sv.z;
    g_ell[dv.w * ELLW + p3] = sv.w;
}

// ---------------- tiled dense transform: g_hs = (X @ W) * dinv[row] --------
// 16-row x 64-col tile, 128 threads, 2x4 thread tile -> 512 CTAs (~43% occ).
template <int LAYER>
__global__ void __launch_bounds__(128) k_xw(const float* __restrict__ Xext,
                                            const float* __restrict__ W) {
    constexpr int K  = (LAYER == 1) ? IN_DIM : HID;
    constexpr int KC = 64;

    __shared__ float Xs[16][KC + 1];
    __shared__ float Ws[KC][64];

    const int tid = threadIdx.x;
    const int tx = tid & 15;             // col group (x4)
    const int ty = tid >> 4;             // row group (x2), 0..7
    const int row0 = blockIdx.x * 16;
    const float* X = (LAYER == 1) ? Xext : g_h1;

    float acc[2][4];
#pragma unroll
    for (int i = 0; i < 2; i++)
#pragma unroll
        for (int j = 0; j < 4; j++) acc[i][j] = 0.0f;

    for (int kc = 0; kc < K; kc += KC) {
        // stage X tile: 16x64 = 256 float4, 2/thread
#pragma unroll
        for (int it = 0; it < 2; it++) {
            int idx = tid + it * 128;
            int r = idx >> 4, c4 = (idx & 15) * 4;
            float4 v = *(const float4*)&X[(long)(row0 + r) * K + kc + c4];
            Xs[r][c4] = v.x; Xs[r][c4 + 1] = v.y; Xs[r][c4 + 2] = v.z; Xs[r][c4 + 3] = v.w;
        }
        // stage W tile: 64x64 = 1024 float4, 8/thread
#pragma unroll
        for (int it = 0; it < 8; it++) {
            int idx = tid + it * 128;
            int k = idx >> 4, c4 = (idx & 15) * 4;
            *(float4*)&Ws[k][c4] = *(const float4*)&W[(long)(kc + k) * HID + c4];
        }
        __syncthreads();

#pragma unroll 8
        for (int k = 0; k < KC; k++) {
            float4 wv = *(const float4*)&Ws[k][tx * 4];
            float xr0 = Xs[ty * 2    ][k];
            float xr1 = Xs[ty * 2 + 1][k];
            acc[0][0] = fmaf(xr0, wv.x, acc[0][0]); acc[0][1] = fmaf(xr0, wv.y, acc[0][1]);
            acc[0][2] = fmaf(xr0, wv.z, acc[0][2]); acc[0][3] = fmaf(xr0, wv.w, acc[0][3]);
            acc[1][0] = fmaf(xr1, wv.x, acc[1][0]); acc[1][1] = fmaf(xr1, wv.y, acc[1][1]);
            acc[1][2] = fmaf(xr1, wv.z, acc[1][2]); acc[1][3] = fmaf(xr1, wv.w, acc[1][3]);
        }
        __syncthreads();
    }

#pragma unroll
    for (int i = 0; i < 2; i++) {
        int row = row0 + ty * 2 + i;
        float dv = rsqrtf((float)g_cnt[row] + 1.0f);
        float4 v = make_float4(acc[i][0] * dv, acc[i][1] * dv,
                               acc[i][2] * dv, acc[i][3] * dv);
        *(float4*)&g_hs[(long)row * HID + tx * 4] = v;
    }
}

// ---------------- warp-per-node gather + fused finalize --------------------
// out[d] = relu(dinv[d]*(hs[d] + sum_{(s,d)} hs[s]) + b)
template <int LAYER>
__global__ void __launch_bounds__(256) k_gather(const float* __restrict__ b) {
    int node = blockIdx.x * 8 + (threadIdx.x >> 5);
    int lane = threadIdx.x & 31;

    const float2* hs2 = (const float2*)g_hs;          // 32 float2 per row
    float2 acc = hs2[(long)node * 32 + lane];         // self loop
    int cnt = g_cnt[node];
    const int* row = g_ell + (long)node * ELLW;

    int j = 0;
    for (; j + 8 <= cnt; j += 8) {
        int s0 = __ldg(&row[j]);
        int s1 = __ldg(&row[j + 1]);
        int s2 = __ldg(&row[j + 2]);
        int s3 = __ldg(&row[j + 3]);
        int s4 = __ldg(&row[j + 4]);
        int s5 = __ldg(&row[j + 5]);
        int s6 = __ldg(&row[j + 6]);
        int s7 = __ldg(&row[j + 7]);
        float2 v0 = __ldg(&hs2[(long)s0 * 32 + lane]);
        float2 v1 = __ldg(&hs2[(long)s1 * 32 + lane]);
        float2 v2 = __ldg(&hs2[(long)s2 * 32 + lane]);
        float2 v3 = __ldg(&hs2[(long)s3 * 32 + lane]);
        float2 v4 = __ldg(&hs2[(long)s4 * 32 + lane]);
        float2 v5 = __ldg(&hs2[(long)s5 * 32 + lane]);
        float2 v6 = __ldg(&hs2[(long)s6 * 32 + lane]);
        float2 v7 = __ldg(&hs2[(long)s7 * 32 + lane]);
        acc.x += ((v0.x + v1.x) + (v2.x + v3.x)) + ((v4.x + v5.x) + (v6.x + v7.x));
        acc.y += ((v0.y + v1.y) + (v2.y + v3.y)) + ((v4.y + v5.y) + (v6.y + v7.y));
    }
    for (; j < cnt; j++) {
        int s = __ldg(&row[j]);
        float2 v = __ldg(&hs2[(long)s * 32 + lane]);
        acc.x += v.x; acc.y += v.y;
    }

    float dv = rsqrtf((float)cnt + 1.0f);
    float2 bb = *(const float2*)&b[lane * 2];
    float vx = fmaxf(fmaf(acc.x, dv, bb.x), 0.0f);
    float vy = fmaxf(fmaf(acc.y, dv, bb.y), 0.0f);
    if (LAYER == 1) {
        ((float2*)g_h1)[(long)node * 32 + lane] = make_float2(vx, vy);
    } else {
        __nv_bfloat162 o = __floats2bfloat162_rn(vx, vy);
        ((__nv_bfloat162*)g_hb)[(long)node * 32 + lane] = o;
        // last consumer of g_cnt this call: reset for the next call's k_ell
        if (lane == 0) g_cnt[node] = 0;
    }
}

// ---------------- sim = sigmoid(h2 @ h2^T), bf16 mma.sync ------------------
__device__ __forceinline__ float sigmoidf_(float x) {
    float t;
    asm("tanh.approx.f32 %0, %1;" : "=f"(t) : "f"(x * 0.5f));
    return fmaf(t, 0.5f, 0.5f);
}

__device__ __forceinline__ void mma_bf16(float c[4], uint32_t a0, uint32_t a1,
                                         uint32_t a2, uint32_t a3,
                                         uint32_t b0, uint32_t b1) {
    asm volatile(
        "mma.sync.aligned.m16n8k16.row.col.f32.bf16.bf16.f32 "
        "{%0,%1,%2,%3},{%4,%5,%6,%7},{%8,%9},{%0,%1,%2,%3};"
        : "+f"(c[0]), "+f"(c[1]), "+f"(c[2]), "+f"(c[3])
        : "r"(a0), "r"(a1), "r"(a2), "r"(a3), "r"(b0), "r"(b1));
}

__global__ void __launch_bounds__(256) k_sim(float* __restrict__ out) {
    __shared__ __nv_bfloat16 As[128][72];
    __shared__ __nv_bfloat16 Bs[128][72];

    int tm = blockIdx.y, tn = blockIdx.x;
    int tid = threadIdx.x;

    const uint4* gA = (const uint4*)(g_hb + (long)tm * 128 * HID);
    const uint4* gB = (const uint4*)(g_hb + (long)tn * 128 * HID);
#pragma unroll
    for (int i = 0; i < 4; i++) {
        int idx = tid + i * 256;
        int r = idx >> 3, c = idx & 7;
        *(uint4*)&As[r][c * 8] = gA[idx];
        *(uint4*)&Bs[r][c * 8] = gB[idx];
    }
    __syncthreads();

    int wid = tid >> 5, lane = tid & 31;
    int wm = wid >> 2, wn = wid & 3;
    int grp = lane >> 2, qp = lane & 3;

    uint32_t a[4][4][4];
#pragma unroll
    for (int mt = 0; mt < 4; mt++) {
        int r0 = wm * 64 + mt * 16 + grp;
#pragma unroll
        for (int kk = 0; kk < 4; kk++) {
            int k0 = kk * 16 + qp * 2;
            a[mt][kk][0] = *(const uint32_t*)&As[r0    ][k0    ];
            a[mt][kk][1] = *(const uint32_t*)&As[r0 + 8][k0    ];
            a[mt][kk][2] = *(const uint32_t*)&As[r0    ][k0 + 8];
            a[mt][kk][3] = *(const uint32_t*)&As[r0 + 8][k0 + 8];
        }
    }

    float acc[4][4][4];
#pragma unroll
    for (int mt = 0; mt < 4; mt++)
#pragma unroll
        for (int nt = 0; nt < 4; nt++)
#pragma unroll
            for (int i = 0; i < 4; i++) acc[mt][nt][i] = 0.0f;

#pragma unroll
    for (int nt = 0; nt < 4; nt++) {
        int n0 = wn * 32 + nt * 8 + grp;
#pragma unroll
        for (int kk = 0; kk < 4; kk++) {
            int k0 = kk * 16 + qp * 2;
            uint32_t b0 = *(const uint32_t*)&Bs[n0][k0    ];
            uint32_t b1 = *(const uint32_t*)&Bs[n0][k0 + 8];
#pragma unroll
            for (int mt = 0; mt < 4; mt++)
                mma_bf16(acc[mt][nt], a[mt][kk][0], a[mt][kk][1],
                         a[mt][kk][2], a[mt][kk][3], b0, b1);
        }
    }

#pragma unroll
    for (int mt = 0; mt < 4; mt++) {
#pragma unroll
        for (int nt = 0; nt < 4; nt++) {
            long r = (long)tm * 128 + wm * 64 + mt * 16 + grp;
            long c = (long)tn * 128 + wn * 32 + nt * 8 + qp * 2;
            float2 v0 = make_float2(sigmoidf_(acc[mt][nt][0]), sigmoidf_(acc[mt][nt][1]));
            float2 v1 = make_float2(sigmoidf_(acc[mt][nt][2]), sigmoidf_(acc[mt][nt][3]));
            *(float2*)&out[r * 8192 + c]       = v0;
            *(float2*)&out[(r + 8) * 8192 + c] = v1;
        }
    }
}

// ---------------- launch ----------------------------------------------------
extern "C" void kernel_launch(void* const* d_in, const int* in_sizes, int n_in,
                              void* d_out, int out_size) {
    const float* x  = (const float*)d_in[0];
    const int*   ei = (const int*)d_in[1];     // int32 (JAX x64 disabled)
    const float* W1 = (const float*)d_in[2];
    const float* b1 = (const float*)d_in[3];
    const float* W2 = (const float*)d_in[4];
    const float* b2 = (const float*)d_in[5];
    float* out = (float*)d_out;

    // ---- ELL build (g_cnt is zero: initial load or reset by prior gather<2>)
    k_ell<<<(E_EDGES / 4) / 256, 256>>>(ei);

    // ---- layer 1
    k_xw<1><<<N_NODES / 16, 128>>>(x, W1);
    k_gather<1><<<N_NODES / 8, 256>>>(b1);

    // ---- layer 2
    k_xw<2><<<N_NODES / 16, 128>>>(nullptr, W2);
    k_gather<2><<<N_NODES / 8, 256>>>(b2);

    // ---- sim = sigmoid(h2 @ h2^T)
    dim3 grid(64, 64);
    k_sim<<<grid, 256>>>(out);
}